// round 5
// baseline (speedup 1.0000x reference)
#include <cuda_runtime.h>
#include <cuda_bf16.h>
#include <math.h>

#define N_NODES 10000
#define E_EDGES 160000
#define C_IN    256
#define C_MID   512

// ---------------- scratch (static __device__ allocations only) ----------------
__device__ float d_xl1[(size_t)N_NODES * C_MID];   // x @ W1^T
__device__ float d_h1 [(size_t)N_NODES * C_MID];   // aggregated layer1 (pre-BN)
__device__ float d_xl2[(size_t)N_NODES * C_IN];    // h1n @ W2^T
__device__ float d_h2 [(size_t)N_NODES * C_IN];    // aggregated layer2 (pre-BN)
__device__ int   d_cnt[N_NODES];
__device__ int   d_off[N_NODES + 1];
__device__ int   d_cur[N_NODES];
__device__ float d_dis[N_NODES];                   // deg^-0.5 (incl self loop)
__device__ int   d_esrc[E_EDGES];                  // CSR-by-dst source rows
__device__ float d_sum[2 * C_MID];                 // BN sums: [0..F)=sum, [F..2F)=sumsq
__device__ float d_ab [2 * C_MID];                 // BN affine: [0..F)=a, [F..2F)=b

// ---------------- init: zero counters & BN sums ----------------
__global__ void k_init() {
    int i = blockIdx.x * blockDim.x + threadIdx.x;
    if (i < N_NODES) d_cnt[i] = 0;
    if (i < 2 * C_MID) d_sum[i] = 0.f;
}

// ---------------- degree count (in-degree over col) ----------------
__global__ void k_count(const int* __restrict__ es) {
    int e = blockIdx.x * blockDim.x + threadIdx.x;
    if (e < E_EDGES) {
        unsigned c = (unsigned)es[E_EDGES + e];
        if (c < N_NODES) atomicAdd(&d_cnt[c], 1);
    }
}

// ---------------- exclusive scan (single block) + dis ----------------
__global__ void k_scan() {
    __shared__ int sh[1024];
    int t = threadIdx.x;
    const int CH = (N_NODES + 1023) / 1024;  // 10
    int base = t * CH;
    int loc = 0;
    for (int i = 0; i < CH; i++) {
        int idx = base + i;
        if (idx < N_NODES) loc += d_cnt[idx];
    }
    sh[t] = loc;
    __syncthreads();
    // Hillis-Steele inclusive scan over 1024 partials
    for (int s = 1; s < 1024; s <<= 1) {
        int v = (t >= s) ? sh[t - s] : 0;
        __syncthreads();
        sh[t] += v;
        __syncthreads();
    }
    int run = (t == 0) ? 0 : sh[t - 1];
    for (int i = 0; i < CH; i++) {
        int idx = base + i;
        if (idx < N_NODES) {
            d_off[idx] = run;
            d_cur[idx] = run;
            int c = d_cnt[idx];
            d_dis[idx] = rsqrtf((float)(c + 1));   // +1 self loop; always > 0
            run += c;
        }
    }
    if (t == 1023) d_off[N_NODES] = sh[1023];
}

// ---------------- CSR fill (order nondeterministic; fp-tolerance absorbs it) --
__global__ void k_fill(const int* __restrict__ es) {
    int e = blockIdx.x * blockDim.x + threadIdx.x;
    if (e < E_EDGES) {
        unsigned r = (unsigned)es[e];
        unsigned c = (unsigned)es[E_EDGES + e];
        if (r < N_NODES && c < N_NODES) {
            int p = atomicAdd(&d_cur[c], 1);
            d_esrc[p] = (int)r;
        }
    }
}

// ---------------- NT GEMM: C[M,Ncols] = A[M,K] * B[Ncols,K]^T ----------------
// BM=BN=64, BK=16, 256 threads, 4x4 microtile.
// LAYER 1: A = x (param), out = d_xl1, no transform.
// LAYER 2: A = d_h1, out = d_xl2, apply relu(a[k]*v + b[k]) on A-load.
template <int K, int LAYER>
__global__ __launch_bounds__(256) void k_gemm(
    const float* __restrict__ Ain, const float* __restrict__ B,
    int M, int Ncols)
{
    const float* __restrict__ A = (LAYER == 1) ? Ain : d_h1;
    float* __restrict__ Cm = (LAYER == 1) ? d_xl1 : d_xl2;

    __shared__ float As[16][68];
    __shared__ float Bs[16][68];
    const int bm = blockIdx.y * 64, bn = blockIdx.x * 64;
    const int tid = threadIdx.x;
    const int lr = tid >> 2;          // 0..63 row within tile
    const int lk = (tid & 3) * 4;     // 0,4,8,12 k-offset within BK
    const int ty = tid >> 4;          // 0..15
    const int tx = tid & 15;          // 0..15

    float acc[4][4];
#pragma unroll
    for (int i = 0; i < 4; i++)
#pragma unroll
        for (int j = 0; j < 4; j++) acc[i][j] = 0.f;

    for (int k0 = 0; k0 < K; k0 += 16) {
        float4 av = make_float4(0.f, 0.f, 0.f, 0.f);
        const int ar = bm + lr;
        if (ar < M) av = *(const float4*)&A[(size_t)ar * K + k0 + lk];
        if (LAYER == 2) {
            const float4 a4 = *(const float4*)&d_ab[k0 + lk];
            const float4 b4 = *(const float4*)&d_ab[C_MID + k0 + lk];
            av.x = fmaxf(av.x * a4.x + b4.x, 0.f);
            av.y = fmaxf(av.y * a4.y + b4.y, 0.f);
            av.z = fmaxf(av.z * a4.z + b4.z, 0.f);
            av.w = fmaxf(av.w * a4.w + b4.w, 0.f);
        }
        const float4 bv = *(const float4*)&B[(size_t)(bn + lr) * K + k0 + lk];

        __syncthreads();
        As[lk + 0][lr] = av.x; As[lk + 1][lr] = av.y;
        As[lk + 2][lr] = av.z; As[lk + 3][lr] = av.w;
        Bs[lk + 0][lr] = bv.x; Bs[lk + 1][lr] = bv.y;
        Bs[lk + 2][lr] = bv.z; Bs[lk + 3][lr] = bv.w;
        __syncthreads();

#pragma unroll
        for (int kk = 0; kk < 16; kk++) {
            const float4 a4 = *(const float4*)&As[kk][ty * 4];
            const float4 b4 = *(const float4*)&Bs[kk][tx * 4];
            float a[4] = {a4.x, a4.y, a4.z, a4.w};
            float b[4] = {b4.x, b4.y, b4.z, b4.w};
#pragma unroll
            for (int i = 0; i < 4; i++)
#pragma unroll
                for (int j = 0; j < 4; j++) acc[i][j] = fmaf(a[i], b[j], acc[i][j]);
        }
    }

#pragma unroll
    for (int i = 0; i < 4; i++) {
        const int r = bm + ty * 4 + i;
        if (r < M) {
            float4 v = make_float4(acc[i][0], acc[i][1], acc[i][2], acc[i][3]);
            *(float4*)&Cm[(size_t)r * Ncols + bn + tx * 4] = v;
        }
    }
}

// ---------------- CSR gather: h[v] = dis[v] * (sum_e dis[src]*xl[src] + dis[v]*xl[v])
template <int F, int VEC>
__global__ __launch_bounds__(F / VEC) void k_agg() {
    const float* __restrict__ xl = (F == C_MID) ? d_xl1 : d_xl2;
    float* __restrict__ h = (F == C_MID) ? d_h1 : d_h2;

    const int v = blockIdx.x;
    const int off = threadIdx.x * VEC;
    float acc[VEC];
#pragma unroll
    for (int i = 0; i < VEC; i++) acc[i] = 0.f;

    const int beg = d_off[v], end = d_off[v + 1];
    const float dv = d_dis[v];

    for (int e = beg; e < end; e++) {
        const int s = d_esrc[e];
        const float w = d_dis[s];
        const float* p = &xl[(size_t)s * F + off];
        if (VEC == 4) {
            const float4 q = *(const float4*)p;
            acc[0] = fmaf(w, q.x, acc[0]); acc[1] = fmaf(w, q.y, acc[1]);
            acc[2] = fmaf(w, q.z, acc[2]); acc[3] = fmaf(w, q.w, acc[3]);
        } else {
            const float2 q = *(const float2*)p;
            acc[0] = fmaf(w, q.x, acc[0]); acc[1] = fmaf(w, q.y, acc[1]);
        }
    }
    // self loop (weight dis[v])
    {
        const float* p = &xl[(size_t)v * F + off];
        if (VEC == 4) {
            const float4 q = *(const float4*)p;
            acc[0] = fmaf(dv, q.x, acc[0]); acc[1] = fmaf(dv, q.y, acc[1]);
            acc[2] = fmaf(dv, q.z, acc[2]); acc[3] = fmaf(dv, q.w, acc[3]);
        } else {
            const float2 q = *(const float2*)p;
            acc[0] = fmaf(dv, q.x, acc[0]); acc[1] = fmaf(dv, q.y, acc[1]);
        }
    }
    float* o = &h[(size_t)v * F + off];
    if (VEC == 4) {
        float4 r = make_float4(dv * acc[0], dv * acc[1], dv * acc[2], dv * acc[3]);
        *(float4*)o = r;
    } else {
        float2 r = make_float2(dv * acc[0], dv * acc[1]);
        *(float2*)o = r;
    }
}

// ---------------- BN stats: per-feature sum & sumsq over rows ----------------
template <int F>
__global__ __launch_bounds__(256) void k_bnstats() {
    const float* __restrict__ h = (F == C_MID) ? d_h1 : d_h2;
    constexpr int FPT = F / 256;
    float s[FPT], q[FPT];
#pragma unroll
    for (int i = 0; i < FPT; i++) { s[i] = 0.f; q[i] = 0.f; }
    for (int r = blockIdx.x; r < N_NODES; r += gridDim.x) {
#pragma unroll
        for (int i = 0; i < FPT; i++) {
            const float v = h[(size_t)r * F + threadIdx.x + i * 256];
            s[i] += v; q[i] = fmaf(v, v, q[i]);
        }
    }
#pragma unroll
    for (int i = 0; i < FPT; i++) {
        atomicAdd(&d_sum[threadIdx.x + i * 256], s[i]);
        atomicAdd(&d_sum[F + threadIdx.x + i * 256], q[i]);
    }
}

// ---------------- BN finalize: a = g*rsqrt(var+eps), b = beta - mean*a -------
__global__ void k_bnfinal(const float* __restrict__ g, const float* __restrict__ be, int F) {
    const int f = threadIdx.x + blockIdx.x * blockDim.x;
    if (f >= F) return;
    const float invN = 1.f / (float)N_NODES;
    const float s = d_sum[f], q = d_sum[F + f];
    const float m = s * invN;
    const float var = q * invN - m * m;
    const float a = g[f] * rsqrtf(var + 1e-5f);
    d_ab[f] = a;
    d_ab[F + f] = be[f] - m * a;
    d_sum[f] = 0.f;            // reset for next BN pass
    d_sum[F + f] = 0.f;
}

// ---------------- final: out = relu(a2*h2 + b2 + x) ----------------
__global__ __launch_bounds__(256) void k_final(const float* __restrict__ x,
                                               float* __restrict__ out) {
    const int idx = blockIdx.x * 256 + threadIdx.x;   // grid = N_NODES blocks
    const int f = threadIdx.x;
    const float v = fmaf(d_ab[f], d_h2[idx], d_ab[C_IN + f]) + x[idx];
    out[idx] = fmaxf(v, 0.f);
}

// ---------------- launcher (kernel launches ONLY — graph-capture safe) --------
extern "C" void kernel_launch(void* const* d_in, const int* in_sizes, int n_in,
                              void* d_out, int out_size) {
    (void)in_sizes; (void)n_in; (void)out_size;
    const float* x  = (const float*)d_in[0];
    const int*   es = (const int*)d_in[1];      // int32 edge list [2, E]
    const float* W1 = (const float*)d_in[2];
    const float* g1 = (const float*)d_in[3];
    const float* b1 = (const float*)d_in[4];
    const float* W2 = (const float*)d_in[5];
    const float* g2 = (const float*)d_in[6];
    const float* b2 = (const float*)d_in[7];
    float* out = (float*)d_out;

    // graph structure
    k_init<<<(N_NODES + 255) / 256, 256>>>();
    k_count<<<(E_EDGES + 255) / 256, 256>>>(es);
    k_scan<<<1, 1024>>>();
    k_fill<<<(E_EDGES + 255) / 256, 256>>>(es);

    // layer 1: GEMM -> aggregate -> BN stats/finalize
    {
        dim3 grid(C_MID / 64, (N_NODES + 63) / 64);
        k_gemm<C_IN, 1><<<grid, 256>>>(x, W1, N_NODES, C_MID);
    }
    k_agg<C_MID, 4><<<N_NODES, C_MID / 4>>>();
    k_bnstats<C_MID><<<296, 256>>>();
    k_bnfinal<<<1, C_MID>>>(g1, b1, C_MID);

    // layer 2: (BN+ReLU fused into A-load) GEMM -> aggregate -> BN -> residual
    {
        dim3 grid(C_IN / 64, (N_NODES + 63) / 64);
        k_gemm<C_MID, 2><<<grid, 256>>>(nullptr, W2, N_NODES, C_IN);
    }
    k_agg<C_IN, 2><<<N_NODES, C_IN / 2>>>();
    k_bnstats<C_IN><<<296, 256>>>();
    k_bnfinal<<<1, C_IN>>>(g2, b2, C_IN);
    k_final<<<N_NODES, 256>>>(x, out);
}

// round 6
// speedup vs baseline: 1.2228x; 1.2228x over previous
#include <cuda_runtime.h>
#include <cuda_bf16.h>
#include <math.h>

#define N_NODES 10000
#define E_EDGES 160000
#define C_IN    256
#define C_MID   512

// ---------------- scratch (static __device__ allocations only) ----------------
__device__ float d_xl1[(size_t)N_NODES * C_MID];   // x @ W1^T
__device__ float d_h1 [(size_t)N_NODES * C_MID];   // aggregated layer1 (pre-BN)
__device__ float d_xl2[(size_t)N_NODES * C_IN];    // h1n @ W2^T
__device__ float d_h2 [(size_t)N_NODES * C_IN];    // aggregated layer2 (pre-BN)
__device__ int   d_cnt[N_NODES];
__device__ int   d_off[N_NODES + 1];
__device__ int   d_cur[N_NODES];
__device__ float d_dis[N_NODES];                   // deg^-0.5 (incl self loop)
__device__ int   d_esrc[E_EDGES];                  // CSR-by-dst source rows
__device__ float d_sum[2 * C_MID];                 // BN sums: [0..F)=sum, [F..2F)=sumsq
__device__ float d_ab [2 * C_MID];                 // BN affine: [0..F)=a, [F..2F)=b

// ---------------- packed f32x2 helpers (FFMA2 path, fp32-exact) ---------------
__device__ __forceinline__ unsigned long long pk2(float lo, float hi) {
    unsigned long long r;
    asm("mov.b64 %0, {%1, %2};" : "=l"(r) : "f"(lo), "f"(hi));
    return r;
}
__device__ __forceinline__ void fma2(unsigned long long& d, unsigned long long a,
                                     unsigned long long b) {
    asm("fma.rn.f32x2 %0, %1, %2, %0;" : "+l"(d) : "l"(a), "l"(b));
}
__device__ __forceinline__ void upk2(float& lo, float& hi, unsigned long long v) {
    asm("mov.b64 {%0, %1}, %2;" : "=f"(lo), "=f"(hi) : "l"(v));
}

// ---------------- init: zero counters & BN sums ----------------
__global__ void k_init() {
    int i = blockIdx.x * blockDim.x + threadIdx.x;
    if (i < N_NODES) d_cnt[i] = 0;
    if (i < 2 * C_MID) d_sum[i] = 0.f;
}

// ---------------- degree count (in-degree over col) ----------------
__global__ void k_count(const int* __restrict__ es) {
    int e = blockIdx.x * blockDim.x + threadIdx.x;
    if (e < E_EDGES) {
        unsigned c = (unsigned)es[E_EDGES + e];
        if (c < N_NODES) atomicAdd(&d_cnt[c], 1);
    }
}

// ---------------- exclusive scan (single block) + dis ----------------
__global__ void k_scan() {
    __shared__ int sh[1024];
    int t = threadIdx.x;
    const int CH = (N_NODES + 1023) / 1024;  // 10
    int base = t * CH;
    int loc = 0;
    for (int i = 0; i < CH; i++) {
        int idx = base + i;
        if (idx < N_NODES) loc += d_cnt[idx];
    }
    sh[t] = loc;
    __syncthreads();
    for (int s = 1; s < 1024; s <<= 1) {
        int v = (t >= s) ? sh[t - s] : 0;
        __syncthreads();
        sh[t] += v;
        __syncthreads();
    }
    int run = (t == 0) ? 0 : sh[t - 1];
    for (int i = 0; i < CH; i++) {
        int idx = base + i;
        if (idx < N_NODES) {
            d_off[idx] = run;
            d_cur[idx] = run;
            int c = d_cnt[idx];
            d_dis[idx] = rsqrtf((float)(c + 1));   // +1 self loop; always > 0
            run += c;
        }
    }
    if (t == 1023) d_off[N_NODES] = sh[1023];
}

// ---------------- CSR fill ----------------
__global__ void k_fill(const int* __restrict__ es) {
    int e = blockIdx.x * blockDim.x + threadIdx.x;
    if (e < E_EDGES) {
        unsigned r = (unsigned)es[e];
        unsigned c = (unsigned)es[E_EDGES + e];
        if (r < N_NODES && c < N_NODES) {
            int p = atomicAdd(&d_cur[c], 1);
            d_esrc[p] = (int)r;
        }
    }
}

// ---------------- NT GEMM: C[M,Ncols] = A[M,K] * B[Ncols,K]^T ----------------
// Tile 64(M) x 128(N), BK=16, 256 threads (16x16), microtile 4x8 via f32x2 pairs.
// Double-buffered smem, k-major staging (transposed on store).
// LAYER 1: A = x, out = d_xl1. LAYER 2: A = d_h1 with relu(a*v+b) fused, out = d_xl2.
template <int K, int LAYER>
__global__ __launch_bounds__(256, 3) void k_gemm(
    const float* __restrict__ Ain, const float* __restrict__ B,
    int M, int Ncols)
{
    const float* __restrict__ A = (LAYER == 1) ? Ain : d_h1;
    float* __restrict__ Cm = (LAYER == 1) ? d_xl1 : d_xl2;

    __shared__ float As[2][16][68];    // [kk][row 0..63]
    __shared__ float Bs[2][16][132];   // [kk][col 0..127]

    const int bm = blockIdx.y * 64, bn = blockIdx.x * 128;
    const int tid = threadIdx.x;
    const int tx = tid & 15, ty = tid >> 4;

    // global-load mapping
    const int ar  = tid >> 2;          // 0..63   A row
    const int akq = (tid & 3) << 2;    // 0,4,8,12
    const int br0 = tid >> 2;          // 0..63   B rows (two halves)
    const int br1 = br0 + 64;

    unsigned long long acc[2][8];
#pragma unroll
    for (int i = 0; i < 2; i++)
#pragma unroll
        for (int j = 0; j < 8; j++) acc[i][j] = 0ull;

    float4 ra, rb0, rb1;

    auto gload = [&](int k0) {
        const int r = bm + ar;
        ra = make_float4(0.f, 0.f, 0.f, 0.f);
        if (r < M) ra = *(const float4*)&A[(size_t)r * K + k0 + akq];
        if (LAYER == 2) {
            const float4 s4 = *(const float4*)&d_ab[k0 + akq];
            const float4 t4 = *(const float4*)&d_ab[C_MID + k0 + akq];
            ra.x = fmaxf(fmaf(ra.x, s4.x, t4.x), 0.f);
            ra.y = fmaxf(fmaf(ra.y, s4.y, t4.y), 0.f);
            ra.z = fmaxf(fmaf(ra.z, s4.z, t4.z), 0.f);
            ra.w = fmaxf(fmaf(ra.w, s4.w, t4.w), 0.f);
        }
        rb0 = *(const float4*)&B[(size_t)(bn + br0) * K + k0 + akq];
        rb1 = *(const float4*)&B[(size_t)(bn + br1) * K + k0 + akq];
    };
    auto sstore = [&](int buf) {
        As[buf][akq + 0][ar] = ra.x;  As[buf][akq + 1][ar] = ra.y;
        As[buf][akq + 2][ar] = ra.z;  As[buf][akq + 3][ar] = ra.w;
        Bs[buf][akq + 0][br0] = rb0.x; Bs[buf][akq + 1][br0] = rb0.y;
        Bs[buf][akq + 2][br0] = rb0.z; Bs[buf][akq + 3][br0] = rb0.w;
        Bs[buf][akq + 0][br1] = rb1.x; Bs[buf][akq + 1][br1] = rb1.y;
        Bs[buf][akq + 2][br1] = rb1.z; Bs[buf][akq + 3][br1] = rb1.w;
    };

    gload(0);
    sstore(0);
    __syncthreads();

    constexpr int NKT = K / 16;
#pragma unroll 1
    for (int kt = 0; kt < NKT; kt++) {
        const int buf = kt & 1;
        if (kt + 1 < NKT) gload((kt + 1) * 16);
#pragma unroll
        for (int kk = 0; kk < 16; kk++) {
            const float4 a4 = *(const float4*)&As[buf][kk][ty * 4];
            const float4 b0 = *(const float4*)&Bs[buf][kk][tx * 8];
            const float4 b1 = *(const float4*)&Bs[buf][kk][tx * 8 + 4];
            unsigned long long ap[2] = { pk2(a4.x, a4.y), pk2(a4.z, a4.w) };
            unsigned long long bp[8] = {
                pk2(b0.x, b0.x), pk2(b0.y, b0.y), pk2(b0.z, b0.z), pk2(b0.w, b0.w),
                pk2(b1.x, b1.x), pk2(b1.y, b1.y), pk2(b1.z, b1.z), pk2(b1.w, b1.w) };
#pragma unroll
            for (int i = 0; i < 2; i++)
#pragma unroll
                for (int j = 0; j < 8; j++) fma2(acc[i][j], ap[i], bp[j]);
        }
        if (kt + 1 < NKT) {
            sstore(buf ^ 1);
            __syncthreads();
        }
    }

    // epilogue: acc[iq][j] = rows (ty*4+2iq, ty*4+2iq+1), col tx*8+j
#pragma unroll
    for (int iq = 0; iq < 2; iq++) {
        float lo[8], hi[8];
#pragma unroll
        for (int j = 0; j < 8; j++) upk2(lo[j], hi[j], acc[iq][j]);
        const int r0 = bm + ty * 4 + iq * 2;
        const int r1 = r0 + 1;
        if (r0 < M) {
            float* p = &Cm[(size_t)r0 * Ncols + bn + tx * 8];
            *(float4*)p       = make_float4(lo[0], lo[1], lo[2], lo[3]);
            *(float4*)(p + 4) = make_float4(lo[4], lo[5], lo[6], lo[7]);
        }
        if (r1 < M) {
            float* p = &Cm[(size_t)r1 * Ncols + bn + tx * 8];
            *(float4*)p       = make_float4(hi[0], hi[1], hi[2], hi[3]);
            *(float4*)(p + 4) = make_float4(hi[4], hi[5], hi[6], hi[7]);
        }
    }
}

// ---------------- CSR gather: h[v] = dis[v] * (sum_e dis[src]*xl[src] + dis[v]*xl[v])
// 2x unrolled edge loop for MLP.
template <int F, int VEC>
__global__ __launch_bounds__(F / VEC) void k_agg() {
    const float* __restrict__ xl = (F == C_MID) ? d_xl1 : d_xl2;
    float* __restrict__ h = (F == C_MID) ? d_h1 : d_h2;

    const int v = blockIdx.x;
    const int off = threadIdx.x * VEC;
    float acc[VEC];
#pragma unroll
    for (int i = 0; i < VEC; i++) acc[i] = 0.f;

    const int beg = d_off[v], end = d_off[v + 1];
    const float dv = d_dis[v];

    int e = beg;
    for (; e + 1 < end; e += 2) {
        const int s0 = d_esrc[e];
        const int s1 = d_esrc[e + 1];
        const float w0 = d_dis[s0];
        const float w1 = d_dis[s1];
        const float* p0 = &xl[(size_t)s0 * F + off];
        const float* p1 = &xl[(size_t)s1 * F + off];
        if (VEC == 4) {
            const float4 q0 = *(const float4*)p0;
            const float4 q1 = *(const float4*)p1;
            acc[0] = fmaf(w0, q0.x, acc[0]); acc[1] = fmaf(w0, q0.y, acc[1]);
            acc[2] = fmaf(w0, q0.z, acc[2]); acc[3] = fmaf(w0, q0.w, acc[3]);
            acc[0] = fmaf(w1, q1.x, acc[0]); acc[1] = fmaf(w1, q1.y, acc[1]);
            acc[2] = fmaf(w1, q1.z, acc[2]); acc[3] = fmaf(w1, q1.w, acc[3]);
        } else {
            const float2 q0 = *(const float2*)p0;
            const float2 q1 = *(const float2*)p1;
            acc[0] = fmaf(w0, q0.x, acc[0]); acc[1] = fmaf(w0, q0.y, acc[1]);
            acc[0] = fmaf(w1, q1.x, acc[0]); acc[1] = fmaf(w1, q1.y, acc[1]);
        }
    }
    if (e < end) {
        const int s = d_esrc[e];
        const float w = d_dis[s];
        const float* p = &xl[(size_t)s * F + off];
        if (VEC == 4) {
            const float4 q = *(const float4*)p;
            acc[0] = fmaf(w, q.x, acc[0]); acc[1] = fmaf(w, q.y, acc[1]);
            acc[2] = fmaf(w, q.z, acc[2]); acc[3] = fmaf(w, q.w, acc[3]);
        } else {
            const float2 q = *(const float2*)p;
            acc[0] = fmaf(w, q.x, acc[0]); acc[1] = fmaf(w, q.y, acc[1]);
        }
    }
    // self loop (weight dis[v])
    {
        const float* p = &xl[(size_t)v * F + off];
        if (VEC == 4) {
            const float4 q = *(const float4*)p;
            acc[0] = fmaf(dv, q.x, acc[0]); acc[1] = fmaf(dv, q.y, acc[1]);
            acc[2] = fmaf(dv, q.z, acc[2]); acc[3] = fmaf(dv, q.w, acc[3]);
        } else {
            const float2 q = *(const float2*)p;
            acc[0] = fmaf(dv, q.x, acc[0]); acc[1] = fmaf(dv, q.y, acc[1]);
        }
    }
    float* o = &h[(size_t)v * F + off];
    if (VEC == 4) {
        *(float4*)o = make_float4(dv * acc[0], dv * acc[1], dv * acc[2], dv * acc[3]);
    } else {
        *(float2*)o = make_float2(dv * acc[0], dv * acc[1]);
    }
}

// ---------------- BN stats: per-feature sum & sumsq over rows ----------------
template <int F>
__global__ __launch_bounds__(256) void k_bnstats() {
    const float* __restrict__ h = (F == C_MID) ? d_h1 : d_h2;
    constexpr int FPT = F / 256;
    float s[FPT], q[FPT];
#pragma unroll
    for (int i = 0; i < FPT; i++) { s[i] = 0.f; q[i] = 0.f; }
    for (int r = blockIdx.x; r < N_NODES; r += gridDim.x) {
#pragma unroll
        for (int i = 0; i < FPT; i++) {
            const float v = h[(size_t)r * F + threadIdx.x + i * 256];
            s[i] += v; q[i] = fmaf(v, v, q[i]);
        }
    }
#pragma unroll
    for (int i = 0; i < FPT; i++) {
        atomicAdd(&d_sum[threadIdx.x + i * 256], s[i]);
        atomicAdd(&d_sum[F + threadIdx.x + i * 256], q[i]);
    }
}

// ---------------- BN finalize: a = g*rsqrt(var+eps), b = beta - mean*a -------
__global__ void k_bnfinal(const float* __restrict__ g, const float* __restrict__ be, int F) {
    const int f = threadIdx.x + blockIdx.x * blockDim.x;
    if (f >= F) return;
    const float invN = 1.f / (float)N_NODES;
    const float s = d_sum[f], q = d_sum[F + f];
    const float m = s * invN;
    const float var = q * invN - m * m;
    const float a = g[f] * rsqrtf(var + 1e-5f);
    d_ab[f] = a;
    d_ab[F + f] = be[f] - m * a;
    d_sum[f] = 0.f;
    d_sum[F + f] = 0.f;
}

// ---------------- final: out = relu(a2*h2 + b2 + x) ----------------
__global__ __launch_bounds__(256) void k_final(const float* __restrict__ x,
                                               float* __restrict__ out) {
    const int idx = blockIdx.x * 256 + threadIdx.x;
    const int f = threadIdx.x;
    const float v = fmaf(d_ab[f], d_h2[idx], d_ab[C_IN + f]) + x[idx];
    out[idx] = fmaxf(v, 0.f);
}

// ---------------- launcher (kernel launches ONLY — graph-capture safe) --------
extern "C" void kernel_launch(void* const* d_in, const int* in_sizes, int n_in,
                              void* d_out, int out_size) {
    (void)in_sizes; (void)n_in; (void)out_size;
    const float* x  = (const float*)d_in[0];
    const int*   es = (const int*)d_in[1];      // int32 edge list [2, E]
    const float* W1 = (const float*)d_in[2];
    const float* g1 = (const float*)d_in[3];
    const float* b1 = (const float*)d_in[4];
    const float* W2 = (const float*)d_in[5];
    const float* g2 = (const float*)d_in[6];
    const float* b2 = (const float*)d_in[7];
    float* out = (float*)d_out;

    // graph structure
    k_init<<<(N_NODES + 255) / 256, 256>>>();
    k_count<<<(E_EDGES + 255) / 256, 256>>>(es);
    k_scan<<<1, 1024>>>();
    k_fill<<<(E_EDGES + 255) / 256, 256>>>(es);

    // layer 1: GEMM -> aggregate -> BN stats/finalize
    {
        dim3 grid(C_MID / 128, (N_NODES + 63) / 64);   // (4, 157)
        k_gemm<C_IN, 1><<<grid, 256>>>(x, W1, N_NODES, C_MID);
    }
    k_agg<C_MID, 4><<<N_NODES, C_MID / 4>>>();
    k_bnstats<C_MID><<<296, 256>>>();
    k_bnfinal<<<1, C_MID>>>(g1, b1, C_MID);

    // layer 2: (BN+ReLU fused into A-load) GEMM -> aggregate -> BN -> residual
    {
        dim3 grid(C_IN / 128, (N_NODES + 63) / 64);    // (2, 157)
        k_gemm<C_MID, 2><<<grid, 256>>>(nullptr, W2, N_NODES, C_IN);
    }
    k_agg<C_IN, 2><<<N_NODES, C_IN / 2>>>();
    k_bnstats<C_IN><<<296, 256>>>();
    k_bnfinal<<<1, C_IN>>>(g2, b2, C_IN);
    k_final<<<N_NODES, 256>>>(x, out);
}

// round 7
// speedup vs baseline: 1.2856x; 1.0514x over previous
#include <cuda_runtime.h>
#include <cuda_bf16.h>
#include <math.h>

#define N_NODES 10000
#define E_EDGES 160000
#define C_IN    256
#define C_MID   512

// ---------------- scratch (static __device__ allocations only) ----------------
__device__ float d_agx[(size_t)N_NODES * C_IN];    // Â x           (256-wide)
__device__ float d_h1 [(size_t)N_NODES * C_MID];   // (Âx) W1^T     (pre-BN)
__device__ float d_xl2[(size_t)N_NODES * C_IN];    // h1n W2^T
__device__ float d_h2 [(size_t)N_NODES * C_IN];    // Â xl2         (pre-BN)
__device__ int   d_cnt[N_NODES];
__device__ int   d_off[N_NODES + 1];
__device__ int   d_cur[N_NODES];
__device__ float d_dis[N_NODES];                   // deg^-0.5 (incl self loop)
__device__ int   d_esrc[E_EDGES];                  // CSR-by-dst source rows
__device__ float d_sum[2 * C_MID];                 // BN sums: [0..F)=sum, [F..2F)=sumsq
__device__ float d_ab [2 * C_MID];                 // BN affine: [0..F)=a, [F..2F)=b

// ---------------- packed f32x2 helpers (FFMA2 path, fp32-exact) ---------------
__device__ __forceinline__ unsigned long long pk2(float lo, float hi) {
    unsigned long long r;
    asm("mov.b64 %0, {%1, %2};" : "=l"(r) : "f"(lo), "f"(hi));
    return r;
}
__device__ __forceinline__ void fma2(unsigned long long& d, unsigned long long a,
                                     unsigned long long b) {
    asm("fma.rn.f32x2 %0, %1, %2, %0;" : "+l"(d) : "l"(a), "l"(b));
}
__device__ __forceinline__ void upk2(float& lo, float& hi, unsigned long long v) {
    asm("mov.b64 {%0, %1}, %2;" : "=f"(lo), "=f"(hi) : "l"(v));
}

// ---------------- init: zero counters & BN sums ----------------
__global__ void k_init() {
    int i = blockIdx.x * blockDim.x + threadIdx.x;
    if (i < N_NODES) d_cnt[i] = 0;
    if (i < 2 * C_MID) d_sum[i] = 0.f;
}

// ---------------- degree count (in-degree over col) ----------------
__global__ void k_count(const int* __restrict__ es) {
    int e = blockIdx.x * blockDim.x + threadIdx.x;
    if (e < E_EDGES) {
        unsigned c = (unsigned)es[E_EDGES + e];
        if (c < N_NODES) atomicAdd(&d_cnt[c], 1);
    }
}

// ---------------- exclusive scan (single block) + dis ----------------
__global__ void k_scan() {
    __shared__ int sh[1024];
    int t = threadIdx.x;
    const int CH = (N_NODES + 1023) / 1024;  // 10
    int base = t * CH;
    int loc = 0;
    for (int i = 0; i < CH; i++) {
        int idx = base + i;
        if (idx < N_NODES) loc += d_cnt[idx];
    }
    sh[t] = loc;
    __syncthreads();
    for (int s = 1; s < 1024; s <<= 1) {
        int v = (t >= s) ? sh[t - s] : 0;
        __syncthreads();
        sh[t] += v;
        __syncthreads();
    }
    int run = (t == 0) ? 0 : sh[t - 1];
    for (int i = 0; i < CH; i++) {
        int idx = base + i;
        if (idx < N_NODES) {
            d_off[idx] = run;
            d_cur[idx] = run;
            int c = d_cnt[idx];
            d_dis[idx] = rsqrtf((float)(c + 1));   // +1 self loop; always > 0
            run += c;
        }
    }
    if (t == 1023) d_off[N_NODES] = sh[1023];
}

// ---------------- CSR fill ----------------
__global__ void k_fill(const int* __restrict__ es) {
    int e = blockIdx.x * blockDim.x + threadIdx.x;
    if (e < E_EDGES) {
        unsigned r = (unsigned)es[e];
        unsigned c = (unsigned)es[E_EDGES + e];
        if (r < N_NODES && c < N_NODES) {
            int p = atomicAdd(&d_cur[c], 1);
            d_esrc[p] = (int)r;
        }
    }
}

// ---------------- CSR gather (F=256, VEC=4, 2 nodes/block, 4x edge unroll) ----
// MODE 1: in = x (param), out = d_agx.   MODE 2: in = d_xl2, out = d_h2.
template <int MODE>
__global__ __launch_bounds__(128) void k_agg(const float* __restrict__ xin) {
    const float* __restrict__ in = (MODE == 1) ? xin : d_xl2;
    float* __restrict__ out = (MODE == 1) ? d_agx : d_h2;

    const int v = blockIdx.x * 2 + (threadIdx.x >> 6);   // 64 threads per node
    const int off = (threadIdx.x & 63) * 4;
    if (v >= N_NODES) return;

    float a0 = 0.f, a1 = 0.f, a2 = 0.f, a3 = 0.f;
    const int beg = d_off[v], end = d_off[v + 1];
    const float dv = d_dis[v];

    int e = beg;
    for (; e + 3 < end; e += 4) {
        const int s0 = d_esrc[e + 0];
        const int s1 = d_esrc[e + 1];
        const int s2 = d_esrc[e + 2];
        const int s3 = d_esrc[e + 3];
        const float w0 = d_dis[s0], w1 = d_dis[s1];
        const float w2 = d_dis[s2], w3 = d_dis[s3];
        const float4 q0 = *(const float4*)&in[(size_t)s0 * C_IN + off];
        const float4 q1 = *(const float4*)&in[(size_t)s1 * C_IN + off];
        const float4 q2 = *(const float4*)&in[(size_t)s2 * C_IN + off];
        const float4 q3 = *(const float4*)&in[(size_t)s3 * C_IN + off];
        a0 = fmaf(w0, q0.x, a0); a1 = fmaf(w0, q0.y, a1);
        a2 = fmaf(w0, q0.z, a2); a3 = fmaf(w0, q0.w, a3);
        a0 = fmaf(w1, q1.x, a0); a1 = fmaf(w1, q1.y, a1);
        a2 = fmaf(w1, q1.z, a2); a3 = fmaf(w1, q1.w, a3);
        a0 = fmaf(w2, q2.x, a0); a1 = fmaf(w2, q2.y, a1);
        a2 = fmaf(w2, q2.z, a2); a3 = fmaf(w2, q2.w, a3);
        a0 = fmaf(w3, q3.x, a0); a1 = fmaf(w3, q3.y, a1);
        a2 = fmaf(w3, q3.z, a2); a3 = fmaf(w3, q3.w, a3);
    }
    for (; e < end; e++) {
        const int s = d_esrc[e];
        const float w = d_dis[s];
        const float4 q = *(const float4*)&in[(size_t)s * C_IN + off];
        a0 = fmaf(w, q.x, a0); a1 = fmaf(w, q.y, a1);
        a2 = fmaf(w, q.z, a2); a3 = fmaf(w, q.w, a3);
    }
    {   // self loop
        const float4 q = *(const float4*)&in[(size_t)v * C_IN + off];
        a0 = fmaf(dv, q.x, a0); a1 = fmaf(dv, q.y, a1);
        a2 = fmaf(dv, q.z, a2); a3 = fmaf(dv, q.w, a3);
    }
    *(float4*)&out[(size_t)v * C_IN + off] =
        make_float4(dv * a0, dv * a1, dv * a2, dv * a3);
}

// ---------------- NT GEMM: C[M,Ncols] = A[M,K] * B[Ncols,K]^T ----------------
// Tile 64(M) x 128(N), BK=16, 256 threads, microtile 4x8 via f32x2 pairs.
// LAYER 1: A = d_agx, out = d_h1.  LAYER 2: A = d_h1 + fused relu(a*v+b), out = d_xl2.
template <int K, int LAYER>
__global__ __launch_bounds__(256, 3) void k_gemm(
    const float* __restrict__ B, int M, int Ncols)
{
    const float* __restrict__ A = (LAYER == 1) ? d_agx : d_h1;
    float* __restrict__ Cm = (LAYER == 1) ? d_h1 : d_xl2;

    __shared__ float As[2][16][68];
    __shared__ float Bs[2][16][132];

    const int bm = blockIdx.y * 64, bn = blockIdx.x * 128;
    const int tid = threadIdx.x;
    const int tx = tid & 15, ty = tid >> 4;

    const int ar  = tid >> 2;
    const int akq = (tid & 3) << 2;
    const int br0 = tid >> 2;
    const int br1 = br0 + 64;

    unsigned long long acc[2][8];
#pragma unroll
    for (int i = 0; i < 2; i++)
#pragma unroll
        for (int j = 0; j < 8; j++) acc[i][j] = 0ull;

    float4 ra, rb0, rb1;

    auto gload = [&](int k0) {
        const int r = bm + ar;
        ra = make_float4(0.f, 0.f, 0.f, 0.f);
        if (r < M) ra = *(const float4*)&A[(size_t)r * K + k0 + akq];
        if (LAYER == 2) {
            const float4 s4 = *(const float4*)&d_ab[k0 + akq];
            const float4 t4 = *(const float4*)&d_ab[C_MID + k0 + akq];
            ra.x = fmaxf(fmaf(ra.x, s4.x, t4.x), 0.f);
            ra.y = fmaxf(fmaf(ra.y, s4.y, t4.y), 0.f);
            ra.z = fmaxf(fmaf(ra.z, s4.z, t4.z), 0.f);
            ra.w = fmaxf(fmaf(ra.w, s4.w, t4.w), 0.f);
        }
        rb0 = *(const float4*)&B[(size_t)(bn + br0) * K + k0 + akq];
        rb1 = *(const float4*)&B[(size_t)(bn + br1) * K + k0 + akq];
    };
    auto sstore = [&](int buf) {
        As[buf][akq + 0][ar] = ra.x;  As[buf][akq + 1][ar] = ra.y;
        As[buf][akq + 2][ar] = ra.z;  As[buf][akq + 3][ar] = ra.w;
        Bs[buf][akq + 0][br0] = rb0.x; Bs[buf][akq + 1][br0] = rb0.y;
        Bs[buf][akq + 2][br0] = rb0.z; Bs[buf][akq + 3][br0] = rb0.w;
        Bs[buf][akq + 0][br1] = rb1.x; Bs[buf][akq + 1][br1] = rb1.y;
        Bs[buf][akq + 2][br1] = rb1.z; Bs[buf][akq + 3][br1] = rb1.w;
    };

    gload(0);
    sstore(0);
    __syncthreads();

    constexpr int NKT = K / 16;
#pragma unroll 1
    for (int kt = 0; kt < NKT; kt++) {
        const int buf = kt & 1;
        if (kt + 1 < NKT) gload((kt + 1) * 16);
#pragma unroll
        for (int kk = 0; kk < 16; kk++) {
            const float4 a4 = *(const float4*)&As[buf][kk][ty * 4];
            const float4 b0 = *(const float4*)&Bs[buf][kk][tx * 8];
            const float4 b1 = *(const float4*)&Bs[buf][kk][tx * 8 + 4];
            unsigned long long ap[2] = { pk2(a4.x, a4.y), pk2(a4.z, a4.w) };
            unsigned long long bp[8] = {
                pk2(b0.x, b0.x), pk2(b0.y, b0.y), pk2(b0.z, b0.z), pk2(b0.w, b0.w),
                pk2(b1.x, b1.x), pk2(b1.y, b1.y), pk2(b1.z, b1.z), pk2(b1.w, b1.w) };
#pragma unroll
            for (int i = 0; i < 2; i++)
#pragma unroll
                for (int j = 0; j < 8; j++) fma2(acc[i][j], ap[i], bp[j]);
        }
        if (kt + 1 < NKT) {
            sstore(buf ^ 1);
            __syncthreads();
        }
    }

#pragma unroll
    for (int iq = 0; iq < 2; iq++) {
        float lo[8], hi[8];
#pragma unroll
        for (int j = 0; j < 8; j++) upk2(lo[j], hi[j], acc[iq][j]);
        const int r0 = bm + ty * 4 + iq * 2;
        const int r1 = r0 + 1;
        if (r0 < M) {
            float* p = &Cm[(size_t)r0 * Ncols + bn + tx * 8];
            *(float4*)p       = make_float4(lo[0], lo[1], lo[2], lo[3]);
            *(float4*)(p + 4) = make_float4(lo[4], lo[5], lo[6], lo[7]);
        }
        if (r1 < M) {
            float* p = &Cm[(size_t)r1 * Ncols + bn + tx * 8];
            *(float4*)p       = make_float4(hi[0], hi[1], hi[2], hi[3]);
            *(float4*)(p + 4) = make_float4(hi[4], hi[5], hi[6], hi[7]);
        }
    }
}

// ---------------- BN stats: per-feature sum & sumsq over rows ----------------
template <int F>
__global__ __launch_bounds__(256) void k_bnstats() {
    const float* __restrict__ h = (F == C_MID) ? d_h1 : d_h2;
    constexpr int FPT = F / 256;
    float s[FPT], q[FPT];
#pragma unroll
    for (int i = 0; i < FPT; i++) { s[i] = 0.f; q[i] = 0.f; }
    for (int r = blockIdx.x; r < N_NODES; r += gridDim.x) {
#pragma unroll
        for (int i = 0; i < FPT; i++) {
            const float v = h[(size_t)r * F + threadIdx.x + i * 256];
            s[i] += v; q[i] = fmaf(v, v, q[i]);
        }
    }
#pragma unroll
    for (int i = 0; i < FPT; i++) {
        atomicAdd(&d_sum[threadIdx.x + i * 256], s[i]);
        atomicAdd(&d_sum[F + threadIdx.x + i * 256], q[i]);
    }
}

// ---------------- BN finalize ----------------
__global__ void k_bnfinal(const float* __restrict__ g, const float* __restrict__ be, int F) {
    const int f = threadIdx.x + blockIdx.x * blockDim.x;
    if (f >= F) return;
    const float invN = 1.f / (float)N_NODES;
    const float s = d_sum[f], q = d_sum[F + f];
    const float m = s * invN;
    const float var = q * invN - m * m;
    const float a = g[f] * rsqrtf(var + 1e-5f);
    d_ab[f] = a;
    d_ab[F + f] = be[f] - m * a;
    d_sum[f] = 0.f;
    d_sum[F + f] = 0.f;
}

// ---------------- final: out = relu(a2*h2 + b2 + x) ----------------
__global__ __launch_bounds__(256) void k_final(const float* __restrict__ x,
                                               float* __restrict__ out) {
    const int idx = blockIdx.x * 256 + threadIdx.x;
    const int f = threadIdx.x;
    const float v = fmaf(d_ab[f], d_h2[idx], d_ab[C_IN + f]) + x[idx];
    out[idx] = fmaxf(v, 0.f);
}

// ---------------- launcher (kernel launches ONLY — graph-capture safe) --------
extern "C" void kernel_launch(void* const* d_in, const int* in_sizes, int n_in,
                              void* d_out, int out_size) {
    (void)in_sizes; (void)n_in; (void)out_size;
    const float* x  = (const float*)d_in[0];
    const int*   es = (const int*)d_in[1];      // int32 edge list [2, E]
    const float* W1 = (const float*)d_in[2];
    const float* g1 = (const float*)d_in[3];
    const float* b1 = (const float*)d_in[4];
    const float* W2 = (const float*)d_in[5];
    const float* g2 = (const float*)d_in[6];
    const float* b2 = (const float*)d_in[7];
    float* out = (float*)d_out;

    // graph structure
    k_init<<<(N_NODES + 255) / 256, 256>>>();
    k_count<<<(E_EDGES + 255) / 256, 256>>>(es);
    k_scan<<<1, 1024>>>();
    k_fill<<<(E_EDGES + 255) / 256, 256>>>(es);

    // layer 1: aggregate x (256-wide) -> GEMM -> BN stats/finalize
    k_agg<1><<<(N_NODES + 1) / 2, 128>>>(x);
    {
        dim3 grid(C_MID / 128, (N_NODES + 63) / 64);   // (4, 157)
        k_gemm<C_IN, 1><<<grid, 256>>>(W1, N_NODES, C_MID);
    }
    k_bnstats<C_MID><<<296, 256>>>();
    k_bnfinal<<<1, C_MID>>>(g1, b1, C_MID);

    // layer 2: (BN+ReLU fused) GEMM -> aggregate -> BN -> residual
    {
        dim3 grid(C_IN / 128, (N_NODES + 63) / 64);    // (2, 157)
        k_gemm<C_MID, 2><<<grid, 256>>>(W2, N_NODES, C_IN);
    }
    k_agg<2><<<(N_NODES + 1) / 2, 128>>>(nullptr);
    k_bnstats<C_IN><<<296, 256>>>();
    k_bnfinal<<<1, C_IN>>>(g2, b2, C_IN);
    k_final<<<N_NODES, 256>>>(x, out);
}

// round 8
// speedup vs baseline: 2.0634x; 1.6050x over previous
#include <cuda_runtime.h>
#include <cuda_bf16.h>
#include <math.h>
#include <stdint.h>

#define N_NODES 10000
#define E_EDGES 160000
#define C_IN    256
#define C_MID   512

// ---------------- scratch (static __device__ allocations only) ----------------
__device__ float d_agx[(size_t)N_NODES * C_IN];    // Â x           (256-wide)
__device__ float d_h1 [(size_t)N_NODES * C_MID];   // (Âx) W1^T     (pre-BN)
__device__ float d_xl2[(size_t)N_NODES * C_IN];    // h1n W2^T
__device__ float d_h2 [(size_t)N_NODES * C_IN];    // Â xl2         (pre-BN)
__device__ int   d_cnt[N_NODES];
__device__ int   d_off[N_NODES + 1];
__device__ int   d_cur[N_NODES];
__device__ float d_dis[N_NODES];                   // deg^-0.5 (incl self loop)
__device__ int   d_esrc[E_EDGES];                  // CSR-by-dst source rows
__device__ float d_sum[2 * C_MID];                 // BN sums: [0..F)=sum, [F..2F)=sumsq
__device__ float d_ab [2 * C_MID];                 // BN affine: [0..F)=a, [F..2F)=b

// ---------------- helpers ----------------
__device__ __forceinline__ uint32_t s2u(const void* p) {
    return (uint32_t)__cvta_generic_to_shared(p);
}
__device__ __forceinline__ void bfsplit(float x, __nv_bfloat16& h, __nv_bfloat16& l) {
    h = __float2bfloat16(x);
    l = __float2bfloat16(x - __bfloat162float(h));
}
__device__ __forceinline__ uint32_t pkbf(__nv_bfloat16 a, __nv_bfloat16 b) {
    __nv_bfloat162 v; v.x = a; v.y = b;
    return *(uint32_t*)&v;
}
__device__ __forceinline__ void ldm_x4(uint32_t& r0, uint32_t& r1, uint32_t& r2,
                                       uint32_t& r3, uint32_t addr) {
    asm volatile("ldmatrix.sync.aligned.m8n8.x4.shared.b16 {%0,%1,%2,%3}, [%4];"
                 : "=r"(r0), "=r"(r1), "=r"(r2), "=r"(r3) : "r"(addr));
}
__device__ __forceinline__ void mma_bf16(float* d, const uint32_t* a,
                                         uint32_t b0, uint32_t b1) {
    asm volatile(
        "mma.sync.aligned.m16n8k16.row.col.f32.bf16.bf16.f32 "
        "{%0,%1,%2,%3}, {%4,%5,%6,%7}, {%8,%9}, {%0,%1,%2,%3};"
        : "+f"(d[0]), "+f"(d[1]), "+f"(d[2]), "+f"(d[3])
        : "r"(a[0]), "r"(a[1]), "r"(a[2]), "r"(a[3]), "r"(b0), "r"(b1));
}

// ---------------- init: zero counters & BN sums ----------------
__global__ void k_init() {
    int i = blockIdx.x * blockDim.x + threadIdx.x;
    if (i < N_NODES) d_cnt[i] = 0;
    if (i < 2 * C_MID) d_sum[i] = 0.f;
}

// ---------------- degree count (in-degree over col) ----------------
__global__ void k_count(const int* __restrict__ es) {
    int e = blockIdx.x * blockDim.x + threadIdx.x;
    if (e < E_EDGES) {
        unsigned c = (unsigned)es[E_EDGES + e];
        if (c < N_NODES) atomicAdd(&d_cnt[c], 1);
    }
}

// ---------------- exclusive scan (single block) + dis ----------------
__global__ void k_scan() {
    __shared__ int sh[1024];
    int t = threadIdx.x;
    const int CH = (N_NODES + 1023) / 1024;  // 10
    int base = t * CH;
    int loc = 0;
    for (int i = 0; i < CH; i++) {
        int idx = base + i;
        if (idx < N_NODES) loc += d_cnt[idx];
    }
    sh[t] = loc;
    __syncthreads();
    for (int s = 1; s < 1024; s <<= 1) {
        int v = (t >= s) ? sh[t - s] : 0;
        __syncthreads();
        sh[t] += v;
        __syncthreads();
    }
    int run = (t == 0) ? 0 : sh[t - 1];
    for (int i = 0; i < CH; i++) {
        int idx = base + i;
        if (idx < N_NODES) {
            d_off[idx] = run;
            d_cur[idx] = run;
            int c = d_cnt[idx];
            d_dis[idx] = rsqrtf((float)(c + 1));   // +1 self loop; always > 0
            run += c;
        }
    }
    if (t == 1023) d_off[N_NODES] = sh[1023];
}

// ---------------- CSR fill ----------------
__global__ void k_fill(const int* __restrict__ es) {
    int e = blockIdx.x * blockDim.x + threadIdx.x;
    if (e < E_EDGES) {
        unsigned r = (unsigned)es[e];
        unsigned c = (unsigned)es[E_EDGES + e];
        if (r < N_NODES && c < N_NODES) {
            int p = atomicAdd(&d_cur[c], 1);
            d_esrc[p] = (int)r;
        }
    }
}

// ---------------- CSR gather (F=256, VEC=4, 2 nodes/block, 4x edge unroll) ----
// MODE 1: in = x (param), out = d_agx.   MODE 2: in = d_xl2, out = d_h2.
template <int MODE>
__global__ __launch_bounds__(128) void k_agg(const float* __restrict__ xin) {
    const float* __restrict__ in = (MODE == 1) ? xin : d_xl2;
    float* __restrict__ out = (MODE == 1) ? d_agx : d_h2;

    const int v = blockIdx.x * 2 + (threadIdx.x >> 6);   // 64 threads per node
    const int off = (threadIdx.x & 63) * 4;
    if (v >= N_NODES) return;

    float a0 = 0.f, a1 = 0.f, a2 = 0.f, a3 = 0.f;
    const int beg = d_off[v], end = d_off[v + 1];
    const float dv = d_dis[v];

    int e = beg;
    for (; e + 3 < end; e += 4) {
        const int s0 = d_esrc[e + 0];
        const int s1 = d_esrc[e + 1];
        const int s2 = d_esrc[e + 2];
        const int s3 = d_esrc[e + 3];
        const float w0 = d_dis[s0], w1 = d_dis[s1];
        const float w2 = d_dis[s2], w3 = d_dis[s3];
        const float4 q0 = *(const float4*)&in[(size_t)s0 * C_IN + off];
        const float4 q1 = *(const float4*)&in[(size_t)s1 * C_IN + off];
        const float4 q2 = *(const float4*)&in[(size_t)s2 * C_IN + off];
        const float4 q3 = *(const float4*)&in[(size_t)s3 * C_IN + off];
        a0 = fmaf(w0, q0.x, a0); a1 = fmaf(w0, q0.y, a1);
        a2 = fmaf(w0, q0.z, a2); a3 = fmaf(w0, q0.w, a3);
        a0 = fmaf(w1, q1.x, a0); a1 = fmaf(w1, q1.y, a1);
        a2 = fmaf(w1, q1.z, a2); a3 = fmaf(w1, q1.w, a3);
        a0 = fmaf(w2, q2.x, a0); a1 = fmaf(w2, q2.y, a1);
        a2 = fmaf(w2, q2.z, a2); a3 = fmaf(w2, q2.w, a3);
        a0 = fmaf(w3, q3.x, a0); a1 = fmaf(w3, q3.y, a1);
        a2 = fmaf(w3, q3.z, a2); a3 = fmaf(w3, q3.w, a3);
    }
    for (; e < end; e++) {
        const int s = d_esrc[e];
        const float w = d_dis[s];
        const float4 q = *(const float4*)&in[(size_t)s * C_IN + off];
        a0 = fmaf(w, q.x, a0); a1 = fmaf(w, q.y, a1);
        a2 = fmaf(w, q.z, a2); a3 = fmaf(w, q.w, a3);
    }
    {   // self loop
        const float4 q = *(const float4*)&in[(size_t)v * C_IN + off];
        a0 = fmaf(dv, q.x, a0); a1 = fmaf(dv, q.y, a1);
        a2 = fmaf(dv, q.z, a2); a3 = fmaf(dv, q.w, a3);
    }
    *(float4*)&out[(size_t)v * C_IN + off] =
        make_float4(dv * a0, dv * a1, dv * a2, dv * a3);
}

// ---------------- Tensor-core NT GEMM (bf16-split, fp32-quality) -------------
// C[M,N] = A[M,K] * B[N,K]^T.  Block tile 128x128, BK=32, 8 warps (2x4),
// warp tile 64x32.  D += Ah*Bh + Ah*Bl + Al*Bh  (Al*Bl ~ 2^-18, dropped).
// LAYER 1: A = d_agx, C = d_h1.  LAYER 2: A = d_h1 (+fused relu(a*v+b)), C = d_xl2.
template <int K, int LAYER>
__global__ __launch_bounds__(256) void k_gemm(const float* __restrict__ B,
                                              int M, int Ncols)
{
    const float* __restrict__ A = (LAYER == 1) ? d_agx : d_h1;
    float* __restrict__ Cm = (LAYER == 1) ? d_h1 : d_xl2;

    constexpr int BK  = 32;
    constexpr int LDS = 40;                    // halves per smem row (80B stride)
    __shared__ __nv_bfloat16 sAh[128 * LDS];
    __shared__ __nv_bfloat16 sAl[128 * LDS];
    __shared__ __nv_bfloat16 sBh[128 * LDS];
    __shared__ __nv_bfloat16 sBl[128 * LDS];

    const int bm = blockIdx.y * 128, bn = blockIdx.x * 128;
    const int tid = threadIdx.x;
    const int lane = tid & 31, wid = tid >> 5;
    const int mw = wid >> 2, nw = wid & 3;     // warp grid 2(m) x 4(n)

    float acc[4][4][4];
#pragma unroll
    for (int i = 0; i < 4; i++)
#pragma unroll
        for (int j = 0; j < 4; j++)
#pragma unroll
            for (int q = 0; q < 4; q++) acc[i][j][q] = 0.f;

    // global-load mapping: 2 threads per row, 16 floats each
    const int grow = tid >> 1;                 // 0..127
    const int gk   = (tid & 1) * 16;           // 0 or 16

    float4 ra[4], rb[4];
    auto gload = [&](int k0) {
        const int arow = bm + grow;
        if (arow < M) {
#pragma unroll
            for (int i = 0; i < 4; i++)
                ra[i] = *(const float4*)&A[(size_t)arow * K + k0 + gk + i * 4];
        } else {
#pragma unroll
            for (int i = 0; i < 4; i++) ra[i] = make_float4(0.f, 0.f, 0.f, 0.f);
        }
        if (LAYER == 2) {
#pragma unroll
            for (int i = 0; i < 4; i++) {
                const int kb = k0 + gk + i * 4;
                const float4 s4 = *(const float4*)&d_ab[kb];
                const float4 t4 = *(const float4*)&d_ab[C_MID + kb];
                ra[i].x = fmaxf(fmaf(ra[i].x, s4.x, t4.x), 0.f);
                ra[i].y = fmaxf(fmaf(ra[i].y, s4.y, t4.y), 0.f);
                ra[i].z = fmaxf(fmaf(ra[i].z, s4.z, t4.z), 0.f);
                ra[i].w = fmaxf(fmaf(ra[i].w, s4.w, t4.w), 0.f);
            }
        }
        const int brow = bn + grow;            // always < Ncols (N mult of 128)
#pragma unroll
        for (int i = 0; i < 4; i++)
            rb[i] = *(const float4*)&B[(size_t)brow * K + k0 + gk + i * 4];
    };

    auto sstore = [&]() {
        const int base = grow * LDS + gk;
#pragma unroll
        for (int i = 0; i < 4; i++) {
            __nv_bfloat16 h0, l0, h1, l1, h2, l2, h3, l3;
            bfsplit(ra[i].x, h0, l0); bfsplit(ra[i].y, h1, l1);
            bfsplit(ra[i].z, h2, l2); bfsplit(ra[i].w, h3, l3);
            *(uint2*)&sAh[base + i * 4] = make_uint2(pkbf(h0, h1), pkbf(h2, h3));
            *(uint2*)&sAl[base + i * 4] = make_uint2(pkbf(l0, l1), pkbf(l2, l3));
            bfsplit(rb[i].x, h0, l0); bfsplit(rb[i].y, h1, l1);
            bfsplit(rb[i].z, h2, l2); bfsplit(rb[i].w, h3, l3);
            *(uint2*)&sBh[base + i * 4] = make_uint2(pkbf(h0, h1), pkbf(h2, h3));
            *(uint2*)&sBl[base + i * 4] = make_uint2(pkbf(l0, l1), pkbf(l2, l3));
        }
    };

    const uint32_t uAh = s2u(sAh), uAl = s2u(sAl);
    const uint32_t uBh = s2u(sBh), uBl = s2u(sBl);

    gload(0);
    constexpr int NT = K / BK;
#pragma unroll 1
    for (int kt = 0; kt < NT; kt++) {
        __syncthreads();                       // previous compute done
        sstore();
        __syncthreads();
        if (kt + 1 < NT) gload((kt + 1) * BK); // prefetch overlaps compute

#pragma unroll
        for (int ks = 0; ks < 2; ks++) {       // two k16 steps in BK=32
            const int koff = ks * 16 + ((lane & 16) ? 8 : 0);
            // B fragments: 4 n-frags (h & l)
            uint32_t Bh0[8], Bl0[8];           // [nf2*4 + reg]
#pragma unroll
            for (int nf2 = 0; nf2 < 2; nf2++) {
                const int row = nw * 32 + nf2 * 16 + (lane & 15);
                const uint32_t ad = (uint32_t)(row * LDS + koff) * 2;
                ldm_x4(Bh0[nf2*4+0], Bh0[nf2*4+1], Bh0[nf2*4+2], Bh0[nf2*4+3], uBh + ad);
                ldm_x4(Bl0[nf2*4+0], Bl0[nf2*4+1], Bl0[nf2*4+2], Bl0[nf2*4+3], uBl + ad);
            }
            // frag nf: {r0,r2} = (nf2, nf even), {r1,r3} = odd
#pragma unroll
            for (int mf = 0; mf < 4; mf++) {
                const int arow = mw * 64 + mf * 16 + (lane & 15);
                const uint32_t ad = (uint32_t)(arow * LDS + koff) * 2;
                uint32_t Ah[4], Al[4];
                ldm_x4(Ah[0], Ah[1], Ah[2], Ah[3], uAh + ad);
                ldm_x4(Al[0], Al[1], Al[2], Al[3], uAl + ad);
#pragma unroll
                for (int nf = 0; nf < 4; nf++) {
                    const int b = (nf >> 1) * 4 + (nf & 1);   // r0/r1 of that x4
                    const uint32_t bh0 = Bh0[b], bh1 = Bh0[b + 2];
                    const uint32_t bl0 = Bl0[b], bl1 = Bl0[b + 2];
                    mma_bf16(acc[mf][nf], Ah, bh0, bh1);
                    mma_bf16(acc[mf][nf], Ah, bl0, bl1);
                    mma_bf16(acc[mf][nf], Al, bh0, bh1);
                }
            }
        }
    }

    // epilogue
#pragma unroll
    for (int mf = 0; mf < 4; mf++) {
        const int r0 = bm + mw * 64 + mf * 16 + (lane >> 2);
        const int r1 = r0 + 8;
#pragma unroll
        for (int nf = 0; nf < 4; nf++) {
            const int col = bn + nw * 32 + nf * 8 + (lane & 3) * 2;
            if (r0 < M)
                *(float2*)&Cm[(size_t)r0 * Ncols + col] =
                    make_float2(acc[mf][nf][0], acc[mf][nf][1]);
            if (r1 < M)
                *(float2*)&Cm[(size_t)r1 * Ncols + col] =
                    make_float2(acc[mf][nf][2], acc[mf][nf][3]);
        }
    }
}

// ---------------- BN stats: per-feature sum & sumsq over rows ----------------
template <int F>
__global__ __launch_bounds__(256) void k_bnstats() {
    const float* __restrict__ h = (F == C_MID) ? d_h1 : d_h2;
    constexpr int FPT = F / 256;
    float s[FPT], q[FPT];
#pragma unroll
    for (int i = 0; i < FPT; i++) { s[i] = 0.f; q[i] = 0.f; }
    for (int r = blockIdx.x; r < N_NODES; r += gridDim.x) {
#pragma unroll
        for (int i = 0; i < FPT; i++) {
            const float v = h[(size_t)r * F + threadIdx.x + i * 256];
            s[i] += v; q[i] = fmaf(v, v, q[i]);
        }
    }
#pragma unroll
    for (int i = 0; i < FPT; i++) {
        atomicAdd(&d_sum[threadIdx.x + i * 256], s[i]);
        atomicAdd(&d_sum[F + threadIdx.x + i * 256], q[i]);
    }
}

// ---------------- BN finalize ----------------
__global__ void k_bnfinal(const float* __restrict__ g, const float* __restrict__ be, int F) {
    const int f = threadIdx.x + blockIdx.x * blockDim.x;
    if (f >= F) return;
    const float invN = 1.f / (float)N_NODES;
    const float s = d_sum[f], q = d_sum[F + f];
    const float m = s * invN;
    const float var = q * invN - m * m;
    const float a = g[f] * rsqrtf(var + 1e-5f);
    d_ab[f] = a;
    d_ab[F + f] = be[f] - m * a;
    d_sum[f] = 0.f;
    d_sum[F + f] = 0.f;
}

// ---------------- final: out = relu(a2*h2 + b2 + x) ----------------
__global__ __launch_bounds__(256) void k_final(const float* __restrict__ x,
                                               float* __restrict__ out) {
    const int idx = blockIdx.x * 256 + threadIdx.x;
    const int f = threadIdx.x;
    const float v = fmaf(d_ab[f], d_h2[idx], d_ab[C_IN + f]) + x[idx];
    out[idx] = fmaxf(v, 0.f);
}

// ---------------- launcher (kernel launches ONLY — graph-capture safe) --------
extern "C" void kernel_launch(void* const* d_in, const int* in_sizes, int n_in,
                              void* d_out, int out_size) {
    (void)in_sizes; (void)n_in; (void)out_size;
    const float* x  = (const float*)d_in[0];
    const int*   es = (const int*)d_in[1];      // int32 edge list [2, E]
    const float* W1 = (const float*)d_in[2];
    const float* g1 = (const float*)d_in[3];
    const float* b1 = (const float*)d_in[4];
    const float* W2 = (const float*)d_in[5];
    const float* g2 = (const float*)d_in[6];
    const float* b2 = (const float*)d_in[7];
    float* out = (float*)d_out;

    // graph structure
    k_init<<<(N_NODES + 255) / 256, 256>>>();
    k_count<<<(E_EDGES + 255) / 256, 256>>>(es);
    k_scan<<<1, 1024>>>();
    k_fill<<<(E_EDGES + 255) / 256, 256>>>(es);

    // layer 1: aggregate x (256-wide) -> TC GEMM -> BN stats/finalize
    k_agg<1><<<(N_NODES + 1) / 2, 128>>>(x);
    {
        dim3 grid(C_MID / 128, (N_NODES + 127) / 128);   // (4, 79)
        k_gemm<C_IN, 1><<<grid, 256>>>(W1, N_NODES, C_MID);
    }
    k_bnstats<C_MID><<<296, 256>>>();
    k_bnfinal<<<1, C_MID>>>(g1, b1, C_MID);

    // layer 2: (BN+ReLU fused) TC GEMM -> aggregate -> BN -> residual
    {
        dim3 grid(C_IN / 128, (N_NODES + 127) / 128);    // (2, 79)
        k_gemm<C_MID, 2><<<grid, 256>>>(W2, N_NODES, C_IN);
    }
    k_agg<2><<<(N_NODES + 1) / 2, 128>>>(nullptr);
    k_bnstats<C_IN><<<296, 256>>>();
    k_bnfinal<<<1, C_IN>>>(g2, b2, C_IN);
    k_final<<<N_NODES, 256>>>(x, out);
}